// round 13
// baseline (speedup 1.0000x reference)
#include <cuda_runtime.h>
#include <cuda_bf16.h>
#include <utility>

// DefocusBlur: depthwise 17x17 cross-correlation, reflect-101 borders.
// Input:  d_in[0] = float32 [32,3,512,512]; Output same shape.
//
// Round-12 geometry (KPT=24, transposed tile, LDS.64 row-pair loads),
// dot engine swapped packed-fma2 -> scalar FFMA-immediate:
//  * fma2 needed a mov.b64 {w,w} weight pack per tap (~132 ALU MOV per
//    row-pair, measured alu=39.6%); scalar FFMA with the weight as an
//    immediate runs at rt_SMSP=1 with ZERO weight-materialization cost
//  * float2 LDS.64 still loads both rows of a pair in one instruction;
//    .x/.y are register-pair aliases (no unpack)
//  * horizontal mirror symmetry: pair sums p[j]=v[8-j]+v[8+j] (scalar)
//  * vertical mirror symmetry: row-dot D=dmin(dy) computed once per
//    row-pair, scattered to the <=2 outputs per half that need it

struct WTab { float w[17][17]; };

__host__ __device__ constexpr WTab make_wtab() {
    WTab t{};
    const float g0 = 0.10650698f;
    const float g1 = 0.78698604f;
    const float g[3] = {g0, g1, g0};
    for (int i = 0; i < 17; ++i) {
        for (int j = 0; j < 17; ++j) {
            float s = 0.0f;
            for (int a = 0; a < 3; ++a) {
                for (int b = 0; b < 3; ++b) {
                    int r = i + a - 1;
                    int c = j + b - 1;
                    r = (r < 0) ? -r : ((r > 16) ? 32 - r : r);   // reflect-101
                    c = (c < 0) ? -c : ((c > 16) ? 32 - c : c);
                    const int dy = r - 8;
                    const int dx = c - 8;
                    if (dy * dy + dx * dx <= 64) s += g[a] * g[b];
                }
            }
            t.w[i][j] = s / 197.0f;
        }
    }
    WTab u{};   // symmetrize exactly (canonical quadrant copy)
    for (int i = 0; i < 17; ++i)
        for (int j = 0; j < 17; ++j) {
            const int ci = (i < 16 - i) ? i : 16 - i;
            const int cj = (j < 16 - j) ? j : 16 - j;
            u.w[i][j] = t.w[ci][cj];
        }
    return u;
}

constexpr WTab WT = make_wtab();

__host__ __device__ constexpr int dmin(int dy) { return (dy < 16 - dy) ? dy : 16 - dy; }

#define KPT    24          // outputs per thread (vertical strip)
#define TILE_W 64
#define TILE_H 48          // 2 strips of KPT
#define HALO   8
#define SMW    80          // columns incl halo
#define SMH    64          // rows incl halo (TILE_H + 16)
#define SMHP   66          // padded column stride: even (8B align), 33 odd
                           // 8B units -> conflict-free LDS.64
#define NTHREADS 128       // 64 columns x 2 strips
#define NRP    ((KPT + 16) / 2)   // row-pairs per strip = 20

// Does row-pair M (local rows 2M, 2M+1) need weight-row D?
__host__ __device__ constexpr bool needD(int M, int D) {
    for (int dy = 0; dy <= 16; ++dy) {
        if (dmin(dy) != D) continue;
        const int kl = 2 * M - dy, kh = 2 * M + 1 - dy;
        if ((kl >= 0 && kl < KPT) || (kh >= 0 && kh < KPT)) return true;
    }
    return false;
}
__host__ __device__ constexpr int jfirst(int D) {
    for (int j = 0; j <= 8; ++j) if (WT.w[D][8 + j] != 0.0f) return j;
    return 9;
}

// ---- dot taps: scalar FFMA with immediate weight, both rows ----
template <int D, int J>
__device__ __forceinline__ void dtap(float& lo, float& hi,
                                     const float* pl, const float* ph) {
    if constexpr (J > jfirst(D)) {
        constexpr float w = WT.w[D][8 + J];
        if constexpr (w != 0.0f) {
            lo = fmaf(pl[J], w, lo);
            hi = fmaf(ph[J], w, hi);
        }
    }
}
template <int D, int... Js>
__device__ __forceinline__ void dtaps(float& lo, float& hi,
                                      const float* pl, const float* ph,
                                      std::integer_sequence<int, Js...>) {
    (dtap<D, Js>(lo, hi, pl, ph), ...);
}

// ---- scatter one dot's two halves into the scalar accumulators ----
template <int M, int D, int DY>
__device__ __forceinline__ void scat1(float* acc, float lo, float hi) {
    if constexpr (dmin(DY) == D) {
        constexpr int kl = 2 * M - DY;
        constexpr int kh = 2 * M + 1 - DY;
        if constexpr (kl >= 0 && kl < KPT) acc[kl] += lo;
        if constexpr (kh >= 0 && kh < KPT) acc[kh] += hi;
    }
}
template <int M, int D, int... DYs>
__device__ __forceinline__ void scat(float* acc, float lo, float hi,
                                     std::integer_sequence<int, DYs...>) {
    (scat1<M, D, DYs>(acc, lo, hi), ...);
}

template <int M, int D>
__device__ __forceinline__ void dodot(const float* pl, const float* ph, float* acc) {
    if constexpr (needD(M, D)) {
        constexpr int JF = jfirst(D);
        constexpr float wf = WT.w[D][8 + JF];
        float lo = wf * pl[JF];            // FMUL-imm
        float hi = wf * ph[JF];
        dtaps<D>(lo, hi, pl, ph, std::make_integer_sequence<int, 9>{});
        scat<M, D>(acc, lo, hi, std::make_integer_sequence<int, 17>{});
    }
}
template <int M, int... Ds>
__device__ __forceinline__ void dodots(const float* pl, const float* ph, float* acc,
                                       std::integer_sequence<int, Ds...>) {
    (dodot<M, Ds>(pl, ph, acc), ...);
}

// ---- one row-pair: 17 LDS.64 + 16 FADD pair sums + scalar-imm dots ----
template <int M>
__device__ __forceinline__ void rowpair(const float* __restrict__ colbase, float* acc) {
    // colbase = &S[tx * SMHP + rbase]; column dx at +dx*SMHP, rows 2M,2M+1 at +2M.
    float pl[9], ph[9];
    {
        const float2 c = *reinterpret_cast<const float2*>(colbase + 8 * SMHP + 2 * M);
        pl[0] = c.x; ph[0] = c.y;
    }
    #pragma unroll
    for (int j = 1; j <= 8; ++j) {
        const float2 a = *reinterpret_cast<const float2*>(colbase + (8 - j) * SMHP + 2 * M);
        const float2 b = *reinterpret_cast<const float2*>(colbase + (8 + j) * SMHP + 2 * M);
        pl[j] = a.x + b.x;
        ph[j] = a.y + b.y;
    }
    dodots<M>(pl, ph, acc, std::make_integer_sequence<int, 9>{});
}

template <int... Ms>
__device__ __forceinline__ void rowpairs(const float* __restrict__ colbase, float* acc,
                                         std::integer_sequence<int, Ms...>) {
    (rowpair<Ms>(colbase, acc), ...);
}

__global__ void __launch_bounds__(NTHREADS, 8)
defocus_blur_kernel(const float* __restrict__ in, float* __restrict__ out) {
    __shared__ float S[SMW * SMHP];    // TRANSPOSED: S[x*SMHP + y]

    const int plane = blockIdx.z;                 // 0..95
    const int X0 = blockIdx.x * TILE_W;
    const int Y0 = blockIdx.y * TILE_H;           // last tile partial (528>512)

    const float* __restrict__ ip = in  + (size_t)plane * 512 * 512;
    float* __restrict__       op = out + (size_t)plane * 512 * 512;

    // ---- cooperative transposed tile load, reflect-101 (5120 elems) ----
    for (int idx = threadIdx.x; idx < SMH * SMW; idx += NTHREADS) {
        const int ly = idx / SMW;          // row    (gmem-coalesced in lx)
        const int lx = idx - ly * SMW;     // column
        int gy = Y0 - HALO + ly;           // <= 535, reflect stays valid
        gy = (gy < 0) ? -gy : ((gy > 511) ? 1022 - gy : gy);
        int gx = X0 - HALO + lx;
        gx = (gx < 0) ? -gx : ((gx > 511) ? 1022 - gx : gx);
        S[lx * SMHP + ly] = __ldg(&ip[gy * 512 + gx]);
    }
    __syncthreads();

    const int tx = threadIdx.x & 63;     // output column within tile
    const int ty = threadIdx.x >> 6;     // strip (0..1), KPT outputs each

    float acc[KPT];
    #pragma unroll
    for (int k = 0; k < KPT; ++k) acc[k] = 0.0f;

    // Strip covers padded rows [ty*KPT, ty*KPT + KPT+15] = NRP row-pairs.
    const float* colbase = &S[tx * SMHP + ty * KPT];
    rowpairs(colbase, acc, std::make_integer_sequence<int, NRP>{});

    // ---- store KPT output rows, coalesced 64-wide, y-predicated ----
    const int yo = Y0 + ty * KPT;
    #pragma unroll
    for (int k = 0; k < KPT; ++k) {
        if (yo + k < 512) {
            op[(yo + k) * 512 + X0 + tx] = acc[k];
        }
    }
}

extern "C" void kernel_launch(void* const* d_in, const int* in_sizes, int n_in,
                              void* d_out, int out_size) {
    const float* in = (const float*)d_in[0];
    float* out = (float*)d_out;
    dim3 grid(512 / TILE_W, (512 + TILE_H - 1) / TILE_H, 96);  // 8 x 11 x 96
    defocus_blur_kernel<<<grid, NTHREADS>>>(in, out);
}

// round 14
// speedup vs baseline: 1.0550x; 1.0550x over previous
#include <cuda_runtime.h>
#include <cuda_bf16.h>
#include <utility>

// DefocusBlur: depthwise 17x17 cross-correlation, reflect-101 borders.
// Input:  d_in[0] = float32 [32,3,512,512]; Output same shape.
//
// Round-12 geometry (KPT=24, transposed tile, LDS.64 row-pair loads),
// dot engine swapped packed-fma2 -> scalar FFMA-immediate:
//  * fma2 needed a mov.b64 {w,w} weight pack per tap (~132 ALU MOV per
//    row-pair, measured alu=39.6%); scalar FFMA with the weight as an
//    immediate runs at rt_SMSP=1 with ZERO weight-materialization cost
//  * float2 LDS.64 still loads both rows of a pair in one instruction;
//    .x/.y are register-pair aliases (no unpack)
//  * horizontal mirror symmetry: pair sums p[j]=v[8-j]+v[8+j] (scalar)
//  * vertical mirror symmetry: row-dot D=dmin(dy) computed once per
//    row-pair, scattered to the <=2 outputs per half that need it

struct WTab { float w[17][17]; };

__host__ __device__ constexpr WTab make_wtab() {
    WTab t{};
    const float g0 = 0.10650698f;
    const float g1 = 0.78698604f;
    const float g[3] = {g0, g1, g0};
    for (int i = 0; i < 17; ++i) {
        for (int j = 0; j < 17; ++j) {
            float s = 0.0f;
            for (int a = 0; a < 3; ++a) {
                for (int b = 0; b < 3; ++b) {
                    int r = i + a - 1;
                    int c = j + b - 1;
                    r = (r < 0) ? -r : ((r > 16) ? 32 - r : r);   // reflect-101
                    c = (c < 0) ? -c : ((c > 16) ? 32 - c : c);
                    const int dy = r - 8;
                    const int dx = c - 8;
                    if (dy * dy + dx * dx <= 64) s += g[a] * g[b];
                }
            }
            t.w[i][j] = s / 197.0f;
        }
    }
    WTab u{};   // symmetrize exactly (canonical quadrant copy)
    for (int i = 0; i < 17; ++i)
        for (int j = 0; j < 17; ++j) {
            const int ci = (i < 16 - i) ? i : 16 - i;
            const int cj = (j < 16 - j) ? j : 16 - j;
            u.w[i][j] = t.w[ci][cj];
        }
    return u;
}

constexpr WTab WT = make_wtab();

__host__ __device__ constexpr int dmin(int dy) { return (dy < 16 - dy) ? dy : 16 - dy; }

#define KPT    24          // outputs per thread (vertical strip)
#define TILE_W 64
#define TILE_H 48          // 2 strips of KPT
#define HALO   8
#define SMW    80          // columns incl halo
#define SMH    64          // rows incl halo (TILE_H + 16)
#define SMHP   66          // padded column stride: even (8B align), 33 odd
                           // 8B units -> conflict-free LDS.64
#define NTHREADS 128       // 64 columns x 2 strips
#define NRP    ((KPT + 16) / 2)   // row-pairs per strip = 20

// Does row-pair M (local rows 2M, 2M+1) need weight-row D?
__host__ __device__ constexpr bool needD(int M, int D) {
    for (int dy = 0; dy <= 16; ++dy) {
        if (dmin(dy) != D) continue;
        const int kl = 2 * M - dy, kh = 2 * M + 1 - dy;
        if ((kl >= 0 && kl < KPT) || (kh >= 0 && kh < KPT)) return true;
    }
    return false;
}
__host__ __device__ constexpr int jfirst(int D) {
    for (int j = 0; j <= 8; ++j) if (WT.w[D][8 + j] != 0.0f) return j;
    return 9;
}

// ---- dot taps: scalar FFMA with immediate weight, both rows ----
template <int D, int J>
__device__ __forceinline__ void dtap(float& lo, float& hi,
                                     const float* pl, const float* ph) {
    if constexpr (J > jfirst(D)) {
        constexpr float w = WT.w[D][8 + J];
        if constexpr (w != 0.0f) {
            lo = fmaf(pl[J], w, lo);
            hi = fmaf(ph[J], w, hi);
        }
    }
}
template <int D, int... Js>
__device__ __forceinline__ void dtaps(float& lo, float& hi,
                                      const float* pl, const float* ph,
                                      std::integer_sequence<int, Js...>) {
    (dtap<D, Js>(lo, hi, pl, ph), ...);
}

// ---- scatter one dot's two halves into the scalar accumulators ----
template <int M, int D, int DY>
__device__ __forceinline__ void scat1(float* acc, float lo, float hi) {
    if constexpr (dmin(DY) == D) {
        constexpr int kl = 2 * M - DY;
        constexpr int kh = 2 * M + 1 - DY;
        if constexpr (kl >= 0 && kl < KPT) acc[kl] += lo;
        if constexpr (kh >= 0 && kh < KPT) acc[kh] += hi;
    }
}
template <int M, int D, int... DYs>
__device__ __forceinline__ void scat(float* acc, float lo, float hi,
                                     std::integer_sequence<int, DYs...>) {
    (scat1<M, D, DYs>(acc, lo, hi), ...);
}

template <int M, int D>
__device__ __forceinline__ void dodot(const float* pl, const float* ph, float* acc) {
    if constexpr (needD(M, D)) {
        constexpr int JF = jfirst(D);
        constexpr float wf = WT.w[D][8 + JF];
        float lo = wf * pl[JF];            // FMUL-imm
        float hi = wf * ph[JF];
        dtaps<D>(lo, hi, pl, ph, std::make_integer_sequence<int, 9>{});
        scat<M, D>(acc, lo, hi, std::make_integer_sequence<int, 17>{});
    }
}
template <int M, int... Ds>
__device__ __forceinline__ void dodots(const float* pl, const float* ph, float* acc,
                                       std::integer_sequence<int, Ds...>) {
    (dodot<M, Ds>(pl, ph, acc), ...);
}

// ---- one row-pair: 17 LDS.64 + 16 FADD pair sums + scalar-imm dots ----
template <int M>
__device__ __forceinline__ void rowpair(const float* __restrict__ colbase, float* acc) {
    // colbase = &S[tx * SMHP + rbase]; column dx at +dx*SMHP, rows 2M,2M+1 at +2M.
    float pl[9], ph[9];
    {
        const float2 c = *reinterpret_cast<const float2*>(colbase + 8 * SMHP + 2 * M);
        pl[0] = c.x; ph[0] = c.y;
    }
    #pragma unroll
    for (int j = 1; j <= 8; ++j) {
        const float2 a = *reinterpret_cast<const float2*>(colbase + (8 - j) * SMHP + 2 * M);
        const float2 b = *reinterpret_cast<const float2*>(colbase + (8 + j) * SMHP + 2 * M);
        pl[j] = a.x + b.x;
        ph[j] = a.y + b.y;
    }
    dodots<M>(pl, ph, acc, std::make_integer_sequence<int, 9>{});
}

template <int... Ms>
__device__ __forceinline__ void rowpairs(const float* __restrict__ colbase, float* acc,
                                         std::integer_sequence<int, Ms...>) {
    (rowpair<Ms>(colbase, acc), ...);
}

__global__ void __launch_bounds__(NTHREADS, 8)
defocus_blur_kernel(const float* __restrict__ in, float* __restrict__ out) {
    __shared__ float S[SMW * SMHP];    // TRANSPOSED: S[x*SMHP + y]

    const int plane = blockIdx.z;                 // 0..95
    const int X0 = blockIdx.x * TILE_W;
    const int Y0 = blockIdx.y * TILE_H;           // last tile partial (528>512)

    const float* __restrict__ ip = in  + (size_t)plane * 512 * 512;
    float* __restrict__       op = out + (size_t)plane * 512 * 512;

    // ---- cooperative transposed tile load, reflect-101 (5120 elems) ----
    for (int idx = threadIdx.x; idx < SMH * SMW; idx += NTHREADS) {
        const int ly = idx / SMW;          // row    (gmem-coalesced in lx)
        const int lx = idx - ly * SMW;     // column
        int gy = Y0 - HALO + ly;           // <= 535, reflect stays valid
        gy = (gy < 0) ? -gy : ((gy > 511) ? 1022 - gy : gy);
        int gx = X0 - HALO + lx;
        gx = (gx < 0) ? -gx : ((gx > 511) ? 1022 - gx : gx);
        S[lx * SMHP + ly] = __ldg(&ip[gy * 512 + gx]);
    }
    __syncthreads();

    const int tx = threadIdx.x & 63;     // output column within tile
    const int ty = threadIdx.x >> 6;     // strip (0..1), KPT outputs each

    float acc[KPT];
    #pragma unroll
    for (int k = 0; k < KPT; ++k) acc[k] = 0.0f;

    // Strip covers padded rows [ty*KPT, ty*KPT + KPT+15] = NRP row-pairs.
    const float* colbase = &S[tx * SMHP + ty * KPT];
    rowpairs(colbase, acc, std::make_integer_sequence<int, NRP>{});

    // ---- store KPT output rows, coalesced 64-wide, y-predicated ----
    const int yo = Y0 + ty * KPT;
    #pragma unroll
    for (int k = 0; k < KPT; ++k) {
        if (yo + k < 512) {
            op[(yo + k) * 512 + X0 + tx] = acc[k];
        }
    }
}

extern "C" void kernel_launch(void* const* d_in, const int* in_sizes, int n_in,
                              void* d_out, int out_size) {
    const float* in = (const float*)d_in[0];
    float* out = (float*)d_out;
    dim3 grid(512 / TILE_W, (512 + TILE_H - 1) / TILE_H, 96);  // 8 x 11 x 96
    defocus_blur_kernel<<<grid, NTHREADS>>>(in, out);
}

// round 15
// speedup vs baseline: 1.0563x; 1.0012x over previous
#include <cuda_runtime.h>
#include <cuda_bf16.h>
#include <utility>

// DefocusBlur: depthwise 17x17 cross-correlation, reflect-101 borders.
// Input:  d_in[0] = float32 [32,3,512,512]; Output same shape.
//
// Round-12 geometry (KPT=24, transposed tile, LDS.64 row-pair loads),
// dot engine swapped packed-fma2 -> scalar FFMA-immediate:
//  * fma2 needed a mov.b64 {w,w} weight pack per tap (~132 ALU MOV per
//    row-pair, measured alu=39.6%); scalar FFMA with the weight as an
//    immediate runs at rt_SMSP=1 with ZERO weight-materialization cost
//  * float2 LDS.64 still loads both rows of a pair in one instruction;
//    .x/.y are register-pair aliases (no unpack)
//  * horizontal mirror symmetry: pair sums p[j]=v[8-j]+v[8+j] (scalar)
//  * vertical mirror symmetry: row-dot D=dmin(dy) computed once per
//    row-pair, scattered to the <=2 outputs per half that need it

struct WTab { float w[17][17]; };

__host__ __device__ constexpr WTab make_wtab() {
    WTab t{};
    const float g0 = 0.10650698f;
    const float g1 = 0.78698604f;
    const float g[3] = {g0, g1, g0};
    for (int i = 0; i < 17; ++i) {
        for (int j = 0; j < 17; ++j) {
            float s = 0.0f;
            for (int a = 0; a < 3; ++a) {
                for (int b = 0; b < 3; ++b) {
                    int r = i + a - 1;
                    int c = j + b - 1;
                    r = (r < 0) ? -r : ((r > 16) ? 32 - r : r);   // reflect-101
                    c = (c < 0) ? -c : ((c > 16) ? 32 - c : c);
                    const int dy = r - 8;
                    const int dx = c - 8;
                    if (dy * dy + dx * dx <= 64) s += g[a] * g[b];
                }
            }
            t.w[i][j] = s / 197.0f;
        }
    }
    WTab u{};   // symmetrize exactly (canonical quadrant copy)
    for (int i = 0; i < 17; ++i)
        for (int j = 0; j < 17; ++j) {
            const int ci = (i < 16 - i) ? i : 16 - i;
            const int cj = (j < 16 - j) ? j : 16 - j;
            u.w[i][j] = t.w[ci][cj];
        }
    return u;
}

constexpr WTab WT = make_wtab();

__host__ __device__ constexpr int dmin(int dy) { return (dy < 16 - dy) ? dy : 16 - dy; }

#define KPT    24          // outputs per thread (vertical strip)
#define TILE_W 64
#define TILE_H 48          // 2 strips of KPT
#define HALO   8
#define SMW    80          // columns incl halo
#define SMH    64          // rows incl halo (TILE_H + 16)
#define SMHP   66          // padded column stride: even (8B align), 33 odd
                           // 8B units -> conflict-free LDS.64
#define NTHREADS 128       // 64 columns x 2 strips
#define NRP    ((KPT + 16) / 2)   // row-pairs per strip = 20

// Does row-pair M (local rows 2M, 2M+1) need weight-row D?
__host__ __device__ constexpr bool needD(int M, int D) {
    for (int dy = 0; dy <= 16; ++dy) {
        if (dmin(dy) != D) continue;
        const int kl = 2 * M - dy, kh = 2 * M + 1 - dy;
        if ((kl >= 0 && kl < KPT) || (kh >= 0 && kh < KPT)) return true;
    }
    return false;
}
__host__ __device__ constexpr int jfirst(int D) {
    for (int j = 0; j <= 8; ++j) if (WT.w[D][8 + j] != 0.0f) return j;
    return 9;
}

// ---- dot taps: scalar FFMA with immediate weight, both rows ----
template <int D, int J>
__device__ __forceinline__ void dtap(float& lo, float& hi,
                                     const float* pl, const float* ph) {
    if constexpr (J > jfirst(D)) {
        constexpr float w = WT.w[D][8 + J];
        if constexpr (w != 0.0f) {
            lo = fmaf(pl[J], w, lo);
            hi = fmaf(ph[J], w, hi);
        }
    }
}
template <int D, int... Js>
__device__ __forceinline__ void dtaps(float& lo, float& hi,
                                      const float* pl, const float* ph,
                                      std::integer_sequence<int, Js...>) {
    (dtap<D, Js>(lo, hi, pl, ph), ...);
}

// ---- scatter one dot's two halves into the scalar accumulators ----
template <int M, int D, int DY>
__device__ __forceinline__ void scat1(float* acc, float lo, float hi) {
    if constexpr (dmin(DY) == D) {
        constexpr int kl = 2 * M - DY;
        constexpr int kh = 2 * M + 1 - DY;
        if constexpr (kl >= 0 && kl < KPT) acc[kl] += lo;
        if constexpr (kh >= 0 && kh < KPT) acc[kh] += hi;
    }
}
template <int M, int D, int... DYs>
__device__ __forceinline__ void scat(float* acc, float lo, float hi,
                                     std::integer_sequence<int, DYs...>) {
    (scat1<M, D, DYs>(acc, lo, hi), ...);
}

template <int M, int D>
__device__ __forceinline__ void dodot(const float* pl, const float* ph, float* acc) {
    if constexpr (needD(M, D)) {
        constexpr int JF = jfirst(D);
        constexpr float wf = WT.w[D][8 + JF];
        float lo = wf * pl[JF];            // FMUL-imm
        float hi = wf * ph[JF];
        dtaps<D>(lo, hi, pl, ph, std::make_integer_sequence<int, 9>{});
        scat<M, D>(acc, lo, hi, std::make_integer_sequence<int, 17>{});
    }
}
template <int M, int... Ds>
__device__ __forceinline__ void dodots(const float* pl, const float* ph, float* acc,
                                       std::integer_sequence<int, Ds...>) {
    (dodot<M, Ds>(pl, ph, acc), ...);
}

// ---- one row-pair: 17 LDS.64 + 16 FADD pair sums + scalar-imm dots ----
template <int M>
__device__ __forceinline__ void rowpair(const float* __restrict__ colbase, float* acc) {
    // colbase = &S[tx * SMHP + rbase]; column dx at +dx*SMHP, rows 2M,2M+1 at +2M.
    float pl[9], ph[9];
    {
        const float2 c = *reinterpret_cast<const float2*>(colbase + 8 * SMHP + 2 * M);
        pl[0] = c.x; ph[0] = c.y;
    }
    #pragma unroll
    for (int j = 1; j <= 8; ++j) {
        const float2 a = *reinterpret_cast<const float2*>(colbase + (8 - j) * SMHP + 2 * M);
        const float2 b = *reinterpret_cast<const float2*>(colbase + (8 + j) * SMHP + 2 * M);
        pl[j] = a.x + b.x;
        ph[j] = a.y + b.y;
    }
    dodots<M>(pl, ph, acc, std::make_integer_sequence<int, 9>{});
}

template <int... Ms>
__device__ __forceinline__ void rowpairs(const float* __restrict__ colbase, float* acc,
                                         std::integer_sequence<int, Ms...>) {
    (rowpair<Ms>(colbase, acc), ...);
}

__global__ void __launch_bounds__(NTHREADS, 8)
defocus_blur_kernel(const float* __restrict__ in, float* __restrict__ out) {
    __shared__ float S[SMW * SMHP];    // TRANSPOSED: S[x*SMHP + y]

    const int plane = blockIdx.z;                 // 0..95
    const int X0 = blockIdx.x * TILE_W;
    const int Y0 = blockIdx.y * TILE_H;           // last tile partial (528>512)

    const float* __restrict__ ip = in  + (size_t)plane * 512 * 512;
    float* __restrict__       op = out + (size_t)plane * 512 * 512;

    // ---- cooperative transposed tile load, reflect-101 (5120 elems) ----
    for (int idx = threadIdx.x; idx < SMH * SMW; idx += NTHREADS) {
        const int ly = idx / SMW;          // row    (gmem-coalesced in lx)
        const int lx = idx - ly * SMW;     // column
        int gy = Y0 - HALO + ly;           // <= 535, reflect stays valid
        gy = (gy < 0) ? -gy : ((gy > 511) ? 1022 - gy : gy);
        int gx = X0 - HALO + lx;
        gx = (gx < 0) ? -gx : ((gx > 511) ? 1022 - gx : gx);
        S[lx * SMHP + ly] = __ldg(&ip[gy * 512 + gx]);
    }
    __syncthreads();

    const int tx = threadIdx.x & 63;     // output column within tile
    const int ty = threadIdx.x >> 6;     // strip (0..1), KPT outputs each

    float acc[KPT];
    #pragma unroll
    for (int k = 0; k < KPT; ++k) acc[k] = 0.0f;

    // Strip covers padded rows [ty*KPT, ty*KPT + KPT+15] = NRP row-pairs.
    const float* colbase = &S[tx * SMHP + ty * KPT];
    rowpairs(colbase, acc, std::make_integer_sequence<int, NRP>{});

    // ---- store KPT output rows, coalesced 64-wide, y-predicated ----
    const int yo = Y0 + ty * KPT;
    #pragma unroll
    for (int k = 0; k < KPT; ++k) {
        if (yo + k < 512) {
            op[(yo + k) * 512 + X0 + tx] = acc[k];
        }
    }
}

extern "C" void kernel_launch(void* const* d_in, const int* in_sizes, int n_in,
                              void* d_out, int out_size) {
    const float* in = (const float*)d_in[0];
    float* out = (float*)d_out;
    dim3 grid(512 / TILE_W, (512 + TILE_H - 1) / TILE_H, 96);  // 8 x 11 x 96
    defocus_blur_kernel<<<grid, NTHREADS>>>(in, out);
}